// round 5
// baseline (speedup 1.0000x reference)
#include <cuda_runtime.h>

#define KF_B 2048
#define KF_T 512
#define KF_D 8
#define KF_M 2

// Output layout (float offsets): means, covs, Rs, Hs concatenated.
#define OFF_MEANS 0
#define OFF_COVS  (KF_B * KF_T * KF_D)                       // 8388608
#define OFF_RS    (OFF_COVS + KF_B * KF_T * KF_D * KF_D)     // 75497472
#define OFF_HS    (OFF_RS + KF_B * KF_T * KF_M * KF_M)       // 79691776

#define SCAN_BLOCKS (KF_B / 2)   // 1024 blocks, 2 chains per 32-thread block
#define FILL_BLOCKS 256

typedef unsigned long long ull;

__device__ __forceinline__ ull ff_pack2(float lo, float hi) {
    ull r;
    asm("mov.b64 %0, {%1, %2};" : "=l"(r) : "f"(lo), "f"(hi));
    return r;
}
__device__ __forceinline__ ull ff_dup(float v) { return ff_pack2(v, v); }
__device__ __forceinline__ ull ff_fma2(ull a, ull b, ull c) {
    ull r;
    asm("fma.rn.f32x2 %0, %1, %2, %3;" : "=l"(r) : "l"(a), "l"(b), "l"(c));
    return r;
}
__device__ __forceinline__ ull ff_add2(ull a, ull b) {
    ull r;
    asm("add.rn.f32x2 %0, %1, %2;" : "=l"(r) : "l"(a), "l"(b));
    return r;
}
__device__ __forceinline__ float2 ff_unpack(ull v) {
    float2 r;
    asm("mov.b64 {%0, %1}, %2;" : "=f"(r.x), "=f"(r.y) : "l"(v));
    return r;
}
__device__ __forceinline__ ull shflx8_64(ull v) {
    float2 p = ff_unpack(v);
    p.x = __shfl_xor_sync(0xffffffffu, p.x, 8);
    p.y = __shfl_xor_sync(0xffffffffu, p.y, 8);
    return ff_pack2(p.x, p.y);
}

__global__ void __launch_bounds__(32) kf_kernel(
    const float* __restrict__ xin_g,   // [B,T,M]
    const float* __restrict__ mean0,   // [B,D]
    const float* __restrict__ cov0,    // [B,D,D]
    const float* __restrict__ Fg,      // [D,D]
    const float* __restrict__ Hg,      // [M,D]
    const float* __restrict__ Qg,      // [D,D]
    const float* __restrict__ Rg,      // [M,M]
    float* __restrict__ out)
{
    // ---------------- broadcast-fill blocks (Rs, Hs) ----------------
    if (blockIdx.x >= SCAN_BLOCKS) {
        const size_t BT = (size_t)KF_B * KF_T;
        float4 r4 = *(const float4*)Rg;
        float4 h0v = *(const float4*)(Hg + 0);
        float4 h1v = *(const float4*)(Hg + 4);
        float4 h2v = *(const float4*)(Hg + 8);
        float4 h3v = *(const float4*)(Hg + 12);
        float4* Rs = (float4*)(out + OFF_RS);
        float4* Hs = (float4*)(out + OFF_HS);
        const size_t nthr = (size_t)FILL_BLOCKS * 32;
        const size_t tid  = (size_t)(blockIdx.x - SCAN_BLOCKS) * 32 + threadIdx.x;
        for (size_t i = tid; i < BT; i += nthr)
            Rs[i] = r4;
        for (size_t i = tid; i < BT; i += nthr) {
            float4* p = Hs + i * 4;
            p[0] = h0v; p[1] = h1v; p[2] = h2v; p[3] = h3v;
        }
        return;
    }

    // ---------------- scan: 2 chains/warp, 16 lanes/chain ----------------
    // lane = g*16 + h*8 + e : chain g, half h (j/k range [4h,4h+4)), state row e
    const int lane  = threadIdx.x & 31;
    const int g     = lane >> 4;
    const int sub   = lane & 15;
    const int e     = sub & 7;
    const int h     = sub >> 3;
    const int b     = blockIdx.x * 2 + g;
    const bool h0   = (h == 0);
    const int j0    = 4 * h;
    const int gbase = g * 16;          // shfl.idx source base for this chain

    // ---- loop-invariant registers ----
    float H0h[4], H1h[4];              // H[m][j0+i]
#pragma unroll
    for (int i = 0; i < 4; ++i) { H0h[i] = Hg[j0 + i]; H1h[i] = Hg[8 + j0 + i]; }

    float Frow[8];                     // F[e][:]
#pragma unroll
    for (int j = 0; j < 8; ++j) Frow[j] = Fg[e * 8 + j];
    float Frh[4];                      // F[e][j0+i]
#pragma unroll
    for (int i = 0; i < 4; ++i) Frh[i] = Fg[e * 8 + j0 + i];

    // Fpk[kk][p] = (F[2p][j0+kk], F[2p+1][j0+kk]) — T0 partial operands
    ull Fpk[4][4];
#pragma unroll
    for (int kk = 0; kk < 4; ++kk)
#pragma unroll
        for (int p = 0; p < 4; ++p)
            Fpk[kk][p] = ff_pack2(Fg[(2 * p) * 8 + j0 + kk], Fg[(2 * p + 1) * 8 + j0 + kk]);

    const ull Qp0 = ff_pack2(Qg[e * 8 + j0],     Qg[e * 8 + j0 + 1]);
    const ull Qp1 = ff_pack2(Qg[e * 8 + j0 + 2], Qg[e * 8 + j0 + 3]);

    const float r00 = Rg[0], r01 = Rg[1], r11 = Rg[3];

    // ---- per-chain state ----
    float cov[4];                      // P[e][j0:j0+4]
    {
        float4 c = *(const float4*)(cov0 + b * 64 + e * 8 + j0);
        cov[0]=c.x; cov[1]=c.y; cov[2]=c.z; cov[3]=c.w;
    }
    float mean_e = mean0[b * 8 + e];   // replicated across h

    float* outM = out + OFF_MEANS + (size_t)b * (KF_T * KF_D);
    float* outC = out + OFF_COVS  + (size_t)b * (KF_T * KF_D * KF_D);
    const float* xrow = xin_g + (size_t)b * (KF_T * KF_M);

    // Double-buffered SMEM (single __syncwarp per step; parity flips buffer)
    // sT0: row stride 12 floats (conflict-free for half-row STS.128 / bcast LDS)
    __shared__ __align__(16) float sT0[2][2 * 104];
    __shared__ __align__(16) float sHP[2][2 * 40];

    float2 x = *(const float2*)xrow;   // prefetch t=0

#pragma unroll 1
    for (int t = 0; t < KF_T; ++t) {
        const int pb = t & 1;
        float* T0b = sT0[pb];
        float* HPb = sHP[pb];

        // emit state BEFORE consuming x_t (1-step-ahead semantics)
        if (h0) outM[t * 8 + e] = mean_e;
        *(float4*)(outC + t * 64 + e * 8 + j0) = make_float4(cov[0], cov[1], cov[2], cov[3]);

        const int tn = (t + 1 < KF_T) ? t + 1 : t;
        const float2 xn = *(const float2*)(xrow + tn * 2);

        // ---- mean-slice exchange (early; independent) ----
        float Mu[4];
#pragma unroll
        for (int i = 0; i < 4; ++i)
            Mu[i] = __shfl_sync(0xffffffffu, mean_e, gbase + j0 + i);

        // ---- G-path start: T0 = P * F^T partial over own k-half ----
        ull tp0 = 0ull, tp1 = 0ull, tp2 = 0ull, tp3 = 0ull;
#pragma unroll
        for (int kk = 0; kk < 4; ++kk) {
            const ull ck = ff_dup(cov[kk]);
            tp0 = ff_fma2(ck, Fpk[kk][0], tp0);
            tp1 = ff_fma2(ck, Fpk[kk][1], tp1);
            tp2 = ff_fma2(ck, Fpk[kk][2], tp2);
            tp3 = ff_fma2(ck, Fpk[kk][3], tp3);
        }

        // ---- gain-path start: hp = H * P_row_e partial ----
        float hp0 = 0.f, hp1 = 0.f;
#pragma unroll
        for (int i = 0; i < 4; ++i) {
            hp0 = fmaf(H0h[i], cov[i], hp0);
            hp1 = fmaf(H1h[i], cov[i], hp1);
        }
        hp0 += __shfl_xor_sync(0xffffffffu, hp0, 8);
        hp1 += __shfl_xor_sync(0xffffffffu, hp1, 8);

        // hm = H*mean, fm = (F*mean)[e] — partials + combine
        float hm0 = 0.f, hm1 = 0.f, fm = 0.f;
#pragma unroll
        for (int i = 0; i < 4; ++i) {
            hm0 = fmaf(H0h[i], Mu[i], hm0);
            hm1 = fmaf(H1h[i], Mu[i], hm1);
            fm  = fmaf(Frh[i], Mu[i], fm);
        }
        hm0 += __shfl_xor_sync(0xffffffffu, hm0, 8);
        hm1 += __shfl_xor_sync(0xffffffffu, hm1, 8);
        fm  += __shfl_xor_sync(0xffffffffu, fm,  8);

        // combine T0 partials across h -> full row e in both copies
        tp0 = ff_add2(tp0, shflx8_64(tp0));
        tp1 = ff_add2(tp1, shflx8_64(tp1));
        tp2 = ff_add2(tp2, shflx8_64(tp2));
        tp3 = ff_add2(tp3, shflx8_64(tp3));

        // stores: T0 half-row + hp vectors
        {
            const ull sa = h ? tp2 : tp0;
            const ull sb = h ? tp3 : tp1;
            ulonglong2 st; st.x = sa; st.y = sb;
            *(ulonglong2*)&T0b[g * 104 + e * 12 + j0] = st;
        }
        if (h0) { HPb[g * 40 + e] = hp0; HPb[g * 40 + 8 + e] = hp1; }
        __syncwarp();

        // ---- gain-path: S, a from hp slices ----
        const float4 Ah = *(const float4*)&HPb[g * 40 + j0];       // hp0[j0:j0+4]
        const float4 Bh = *(const float4*)&HPb[g * 40 + 8 + j0];   // hp1[...]
        const float Aa[4] = {Ah.x, Ah.y, Ah.z, Ah.w};
        const float Bb[4] = {Bh.x, Bh.y, Bh.z, Bh.w};

        float S00 = 0.f, S01 = 0.f, S11 = 0.f, a0 = 0.f, a1 = 0.f;
#pragma unroll
        for (int i = 0; i < 4; ++i) {
            S00 = fmaf(H0h[i], Aa[i], S00);
            S01 = fmaf(H1h[i], Aa[i], S01);
            S11 = fmaf(H1h[i], Bb[i], S11);
            a0  = fmaf(Frh[i], Aa[i], a0);     // a0[e] partial = (F hp0)[e]
            a1  = fmaf(Frh[i], Bb[i], a1);
        }
        S00 = r00 + S00 + __shfl_xor_sync(0xffffffffu, S00, 8);
        S01 = r01 + S01 + __shfl_xor_sync(0xffffffffu, S01, 8);
        S11 = r11 + S11 + __shfl_xor_sync(0xffffffffu, S11, 8);
        a0  = a0 + __shfl_xor_sync(0xffffffffu, a0, 8);
        a1  = a1 + __shfl_xor_sync(0xffffffffu, a1, 8);

        const float idet = __fdividef(1.0f, fmaf(S00, S11, -S01 * S01));
        const float u0 = (S11 * a0 - S01 * a1) * idet;   // (F K0)[e]
        const float u1 = (S00 * a1 - S01 * a0) * idet;   // (F K1)[e]
        const float rs0 = x.x - hm0;
        const float rs1 = x.y - hm1;
        mean_e = fmaf(u0, rs0, fmaf(u1, rs1, fm));       // mean_p[e]

        // ---- G-path finish: cov_p = F*T0 + Q, then rank-2 correction ----
        ull cp0 = Qp0, cp1 = Qp1;
#pragma unroll
        for (int k = 0; k < 8; ++k) {
            const ulonglong2 tv = *(const ulonglong2*)&T0b[g * 104 + k * 12 + j0];
            const ull fk = ff_dup(Frow[k]);
            cp0 = ff_fma2(fk, tv.x, cp0);
            cp1 = ff_fma2(fk, tv.y, cp1);
        }

        // a-slices via shfl.idx (a replicated across h, source h=0 lanes)
        float a0s[4], a1s[4];
#pragma unroll
        for (int i = 0; i < 4; ++i) {
            a0s[i] = __shfl_sync(0xffffffffu, a0, gbase + j0 + i);
            a1s[i] = __shfl_sync(0xffffffffu, a1, gbase + j0 + i);
        }
        const ull nu0 = ff_dup(-u0);
        const ull nu1 = ff_dup(-u1);
        cp0 = ff_fma2(nu0, ff_pack2(a0s[0], a0s[1]), cp0);
        cp0 = ff_fma2(nu1, ff_pack2(a1s[0], a1s[1]), cp0);
        cp1 = ff_fma2(nu0, ff_pack2(a0s[2], a0s[3]), cp1);
        cp1 = ff_fma2(nu1, ff_pack2(a1s[2], a1s[3]), cp1);

        {
            const float2 c0 = ff_unpack(cp0), c1 = ff_unpack(cp1);
            cov[0] = c0.x; cov[1] = c0.y; cov[2] = c1.x; cov[3] = c1.y;
        }
        x = xn;
        // Race-freedom: SMEM double-buffered on t-parity — iteration t+1 writes
        // the OTHER buffer, so this iteration's post-barrier reads are safe; the
        // single __syncwarp orders writes->reads within each iteration.
    }
}

extern "C" void kernel_launch(void* const* d_in, const int* in_sizes, int n_in,
                              void* d_out, int out_size)
{
    (void)in_sizes; (void)n_in; (void)out_size;
    const float* xin   = (const float*)d_in[0];
    const float* mean0 = (const float*)d_in[1];
    const float* cov0  = (const float*)d_in[2];
    const float* F     = (const float*)d_in[3];
    const float* H     = (const float*)d_in[4];
    const float* Q     = (const float*)d_in[5];
    const float* R     = (const float*)d_in[6];
    float* out = (float*)d_out;

    kf_kernel<<<SCAN_BLOCKS + FILL_BLOCKS, 32>>>(xin, mean0, cov0, F, H, Q, R, out);
}